// round 2
// baseline (speedup 1.0000x reference)
#include <cuda_runtime.h>
#include <cstdint>

#define NB 16
#define HH 64
#define WW 64
#define CC 256
#define KE 4
#define FF 256
#define K3 2304   // 9*256
#define HW 4096

#define TM 128
#define TN 128
#define KC 32
#define LDA 36
#define LDB 132
#define NCHUNK 72
#define SMEM_BYTES ((2*TM*LDA + 2*KC*LDB)*4)

// ---------------- scratch (no cudaMalloc allowed) ----------------
__device__ __align__(128) float g_partial[NB*32*CC];
__device__ __align__(128) float g_att[NB*KE];
__device__ __align__(128) float g_bias[NB*FF];
__device__ __align__(128) float g_wmix[(size_t)NB*K3*FF];   // 37.75 MB, tf32-rounded

// ---------------- stage 1: partial global-average-pool ----------------
__global__ void pool_partial_kernel(const float* __restrict__ x) {
    int b = blockIdx.x, s = blockIdx.y, t = threadIdx.x;
    const float* p = x + ((size_t)(b*HW + s*128))*CC + t;
    float sum = 0.f;
    #pragma unroll 8
    for (int i = 0; i < 128; i++) sum += p[(size_t)i*CC];
    g_partial[(b*32+s)*CC + t] = sum;
}

// ---------------- stage 2: routing MLP + softmax + bias mix ----------------
__global__ void routing_kernel(const float* __restrict__ w1, const float* __restrict__ b1,
                               const float* __restrict__ w2, const float* __restrict__ b2,
                               const float* __restrict__ biases) {
    __shared__ float pool[CC];
    __shared__ float a1s[64];
    __shared__ float att[KE];
    int b = blockIdx.x, t = threadIdx.x;
    float s = 0.f;
    #pragma unroll
    for (int i = 0; i < 32; i++) s += g_partial[(b*32+i)*CC + t];
    pool[t] = s * (1.0f/4096.0f);
    __syncthreads();
    if (t < 64) {
        float a = b1[t];
        #pragma unroll 8
        for (int c = 0; c < CC; c++) a += pool[c] * w1[c*64 + t];
        a1s[t] = fmaxf(a, 0.f);
    }
    __syncthreads();
    if (t == 0) {
        float lg[KE]; float mx = -1e30f;
        #pragma unroll
        for (int k = 0; k < KE; k++) {
            float v = b2[k];
            for (int j = 0; j < 64; j++) v += a1s[j]*w2[j*KE + k];
            lg[k] = v; mx = fmaxf(mx, v);
        }
        float se = 0.f;
        #pragma unroll
        for (int k = 0; k < KE; k++) { lg[k] = expf(lg[k]-mx); se += lg[k]; }
        #pragma unroll
        for (int k = 0; k < KE; k++) { att[k] = lg[k]/se; g_att[b*KE+k] = att[k]; }
    }
    __syncthreads();
    float bv = 0.f;
    #pragma unroll
    for (int k = 0; k < KE; k++) bv += att[k]*biases[k*FF + t];
    g_bias[b*FF + t] = bv;
}

// ---------------- stage 3: mix expert kernels -> per-sample W (tf32) ----------------
__global__ void mix_kernel(const float* __restrict__ kernels) {
    int r = blockIdx.x, b = blockIdx.y, f = threadIdx.x;
    const float* ab = g_att + b*KE;
    size_t off = (size_t)r*FF + f;
    float s = ab[0]*kernels[off]
            + ab[1]*kernels[off + (size_t)K3*FF]
            + ab[2]*kernels[off + 2*(size_t)K3*FF]
            + ab[3]*kernels[off + 3*(size_t)K3*FF];
    uint32_t u; asm("cvt.rna.tf32.f32 %0, %1;" : "=r"(u) : "f"(s));
    g_wmix[((size_t)b*K3 + r)*FF + f] = __uint_as_float(u);
}

// ---------------- stage 4: implicit-GEMM conv, tf32 mma.sync ----------------
__device__ __forceinline__ uint32_t f2tf32(float f) {
    uint32_t u; asm("cvt.rna.tf32.f32 %0, %1;" : "=r"(u) : "f"(f));
    return u;
}

__global__ __launch_bounds__(256, 1) void conv_kernel(const float* __restrict__ x,
                                                      float* __restrict__ out) {
    extern __shared__ float sm[];
    float* As = sm;                    // [2][TM][LDA]
    float* Bs = sm + 2*TM*LDA;         // [2][KC][LDB]

    const int b = blockIdx.z, mtile = blockIdx.y, ntile = blockIdx.x;
    const int tid = threadIdx.x;
    const int lane = tid & 31, wid = tid >> 5;
    const int wm = wid & 3, wn = wid >> 2;       // 4 M-warps x 2 N-warps
    const int gid = lane >> 2, tig = lane & 3;

    const float* xb = x + (size_t)b*HW*CC;
    const float* Wb = g_wmix + (size_t)b*K3*FF;

    float acc[2][8][4];
    #pragma unroll
    for (int i=0;i<2;i++)
        #pragma unroll
        for (int j=0;j<8;j++)
            #pragma unroll
            for (int q=0;q<4;q++) acc[i][j][q]=0.f;

    // per-thread gmem->smem load coordinates (4 x float4 for A and B each)
    int a_row[4], a_q[4], a_h[4], a_w[4];
    #pragma unroll
    for (int i=0;i<4;i++){
        int idx = i*256 + tid;
        a_row[i] = idx >> 3;
        a_q[i]   = idx & 7;
        int m = mtile*TM + a_row[i];
        a_h[i] = m >> 6;
        a_w[i] = m & 63;
    }
    int b_row[4], b_col[4];
    #pragma unroll
    for (int i=0;i<4;i++){
        int idx = i*256 + tid;
        b_row[i] = idx >> 5;
        b_col[i] = (idx & 31) << 2;
    }

    float4 areg[4], breg[4];

    auto loadG = [&](int chunk){
        int grp = chunk >> 3;            // 0..8 -> (kh,kw)
        int kh = grp/3 - 1, kw = grp%3 - 1;
        int c0 = (chunk & 7) << 5;       // channel base within tap
        #pragma unroll
        for (int i=0;i<4;i++){
            int hh = a_h[i] + kh, ww = a_w[i] + kw;
            if (hh >= 0 && hh < HH && ww >= 0 && ww < WW)
                areg[i] = *reinterpret_cast<const float4*>(
                    xb + ((size_t)(hh*WW+ww))*CC + c0 + a_q[i]*4);
            else
                areg[i] = make_float4(0.f,0.f,0.f,0.f);
        }
        const float* Wc = Wb + ((size_t)chunk*KC)*FF + ntile*TN;
        #pragma unroll
        for (int i=0;i<4;i++)
            breg[i] = *reinterpret_cast<const float4*>(Wc + (size_t)b_row[i]*FF + b_col[i]);
    };

    auto storeS = [&](int buf){
        float* Ab = As + buf*TM*LDA;
        #pragma unroll
        for (int i=0;i<4;i++){
            float4 v = areg[i];
            v.x = __uint_as_float(f2tf32(v.x));
            v.y = __uint_as_float(f2tf32(v.y));
            v.z = __uint_as_float(f2tf32(v.z));
            v.w = __uint_as_float(f2tf32(v.w));
            *reinterpret_cast<float4*>(Ab + a_row[i]*LDA + a_q[i]*4) = v;
        }
        float* Bb = Bs + buf*KC*LDB;
        #pragma unroll
        for (int i=0;i<4;i++)
            *reinterpret_cast<float4*>(Bb + b_row[i]*LDB + b_col[i]) = breg[i];
    };

    auto compute = [&](int buf){
        const float* Ab = As + buf*TM*LDA + (wm*32)*LDA;
        const float* Bb = Bs + buf*KC*LDB + wn*64;
        #pragma unroll
        for (int ks=0; ks<4; ks++){
            int k0 = ks*8;
            uint32_t af[2][4];
            #pragma unroll
            for (int mi=0; mi<2; mi++){
                int r = mi*16 + gid;
                af[mi][0] = __float_as_uint(Ab[r*LDA + k0 + tig]);
                af[mi][1] = __float_as_uint(Ab[(r+8)*LDA + k0 + tig]);
                af[mi][2] = __float_as_uint(Ab[r*LDA + k0 + tig + 4]);
                af[mi][3] = __float_as_uint(Ab[(r+8)*LDA + k0 + tig + 4]);
            }
            uint32_t bf[8][2];
            #pragma unroll
            for (int nj=0; nj<8; nj++){
                int n = nj*8 + gid;
                bf[nj][0] = __float_as_uint(Bb[(k0 + tig)*LDB + n]);
                bf[nj][1] = __float_as_uint(Bb[(k0 + tig + 4)*LDB + n]);
            }
            #pragma unroll
            for (int mi=0; mi<2; mi++)
                #pragma unroll
                for (int nj=0; nj<8; nj++){
                    asm volatile(
                      "mma.sync.aligned.m16n8k8.row.col.f32.tf32.tf32.f32 "
                      "{%0,%1,%2,%3}, {%4,%5,%6,%7}, {%8,%9}, {%0,%1,%2,%3};\n"
                      : "+f"(acc[mi][nj][0]), "+f"(acc[mi][nj][1]),
                        "+f"(acc[mi][nj][2]), "+f"(acc[mi][nj][3])
                      : "r"(af[mi][0]), "r"(af[mi][1]), "r"(af[mi][2]), "r"(af[mi][3]),
                        "r"(bf[nj][0]), "r"(bf[nj][1]));
                }
        }
    };

    loadG(0);
    storeS(0);
    __syncthreads();
    int cur = 0;
    for (int ch = 0; ch < NCHUNK; ch++){
        if (ch + 1 < NCHUNK) loadG(ch+1);
        compute(cur);
        if (ch + 1 < NCHUNK){
            storeS(cur ^ 1);
            __syncthreads();
            cur ^= 1;
        }
    }

    // epilogue: add routed bias, store fp32
    float* ob = out + ((size_t)b*HW + mtile*TM + wm*32)*FF + ntile*TN + wn*64;
    const float* bb = g_bias + b*FF + ntile*TN + wn*64;
    #pragma unroll
    for (int mi=0; mi<2; mi++)
        #pragma unroll
        for (int nj=0; nj<8; nj++){
            int col = nj*8 + tig*2;
            float bv0 = bb[col], bv1 = bb[col+1];
            int r0 = mi*16 + gid;
            float2 v0 = make_float2(acc[mi][nj][0]+bv0, acc[mi][nj][1]+bv1);
            float2 v1 = make_float2(acc[mi][nj][2]+bv0, acc[mi][nj][3]+bv1);
            *reinterpret_cast<float2*>(ob + (size_t)r0*FF + col) = v0;
            *reinterpret_cast<float2*>(ob + (size_t)(r0+8)*FF + col) = v1;
        }
}

// ---------------- launch ----------------
extern "C" void kernel_launch(void* const* d_in, const int* in_sizes, int n_in,
                              void* d_out, int out_size) {
    (void)in_sizes; (void)n_in; (void)out_size;
    const float* x       = (const float*)d_in[0];
    const float* kernels = (const float*)d_in[1];
    const float* biases  = (const float*)d_in[2];
    const float* w1      = (const float*)d_in[3];
    const float* b1      = (const float*)d_in[4];
    const float* w2      = (const float*)d_in[5];
    const float* b2      = (const float*)d_in[6];
    float* out = (float*)d_out;

    pool_partial_kernel<<<dim3(NB,32), 256>>>(x);
    routing_kernel<<<NB, 256>>>(w1, b1, w2, b2, biases);
    mix_kernel<<<dim3(K3,NB), 256>>>(kernels);

    (void)cudaFuncSetAttribute(conv_kernel, cudaFuncAttributeMaxDynamicSharedMemorySize, SMEM_BYTES);
    conv_kernel<<<dim3(2,32,NB), 256, SMEM_BYTES>>>(x, out);
}

// round 4
// speedup vs baseline: 1.3222x; 1.3222x over previous
#include <cuda_runtime.h>
#include <cstdint>

#define NB 16
#define HH 64
#define WW 64
#define CC 256
#define KE 4
#define FFo 256
#define K3 2304   // 9*256
#define HW 4096

#define TM 128
#define TN 128
#define KC 32
#define LDA 36      // floats per A row (conflict-free: 4*gid+tig)
#define LDB 136     // floats per B row (conflict-free: 8*tig+gid)
#define NCHUNK 72
#define A_STAGE_F (TM*LDA)   // 4608
#define B_STAGE_F (KC*LDB)   // 4352
#define SMEM_BYTES (2*(A_STAGE_F + B_STAGE_F)*4)   // 71680

// ---------------- scratch ----------------
__device__ __align__(128) float g_partial[NB*32*CC];
__device__ __align__(128) float g_att[NB*KE];
__device__ __align__(128) float g_bias[NB*FFo];
__device__ __align__(128) float g_xr[(size_t)NB*HW*CC];      // tf32-rounded input
__device__ __align__(128) float g_wmix[(size_t)NB*K3*FFo];   // [b][k][n], tf32-rounded

// ---------------- helpers ----------------
__device__ __forceinline__ uint32_t f2tf32(float f) {
    uint32_t u; asm("cvt.rna.tf32.f32 %0, %1;" : "=r"(u) : "f"(f));
    return u;
}
__device__ __forceinline__ uint32_t s2u(const void* p) {
    uint32_t a;
    asm("{ .reg .u64 t; cvta.to.shared.u64 t, %1; cvt.u32.u64 %0, t; }" : "=r"(a) : "l"(p));
    return a;
}
__device__ __forceinline__ void cp16(uint32_t d, const void* s, uint32_t sz) {
    asm volatile("cp.async.cg.shared.global [%0], [%1], 16, %2;" :: "r"(d), "l"(s), "r"(sz) : "memory");
}

// ---------------- stage 1: pool partials + tf32-rounded input copy ----------------
__global__ void pool_partial_kernel(const float* __restrict__ x) {
    int b = blockIdx.x, s = blockIdx.y, t = threadIdx.x;
    size_t base = ((size_t)(b*HW + s*128))*CC + t;
    float sum = 0.f;
    #pragma unroll 8
    for (int i = 0; i < 128; i++) {
        float v = x[base + (size_t)i*CC];
        sum += v;
        g_xr[base + (size_t)i*CC] = __uint_as_float(f2tf32(v));
    }
    g_partial[(b*32+s)*CC + t] = sum;
}

// ---------------- stage 2: routing MLP + softmax + bias mix ----------------
__global__ void routing_kernel(const float* __restrict__ w1, const float* __restrict__ b1,
                               const float* __restrict__ w2, const float* __restrict__ b2,
                               const float* __restrict__ biases) {
    __shared__ float pool[CC];
    __shared__ float a1s[64];
    __shared__ float att[KE];
    int b = blockIdx.x, t = threadIdx.x;
    float s = 0.f;
    #pragma unroll
    for (int i = 0; i < 32; i++) s += g_partial[(b*32+i)*CC + t];
    pool[t] = s * (1.0f/4096.0f);
    __syncthreads();
    if (t < 64) {
        float a = b1[t];
        #pragma unroll 8
        for (int c = 0; c < CC; c++) a += pool[c] * w1[c*64 + t];
        a1s[t] = fmaxf(a, 0.f);
    }
    __syncthreads();
    if (t == 0) {
        float lg[KE]; float mx = -1e30f;
        #pragma unroll
        for (int k = 0; k < KE; k++) {
            float v = b2[k];
            for (int j = 0; j < 64; j++) v += a1s[j]*w2[j*KE + k];
            lg[k] = v; mx = fmaxf(mx, v);
        }
        float se = 0.f;
        #pragma unroll
        for (int k = 0; k < KE; k++) { lg[k] = expf(lg[k]-mx); se += lg[k]; }
        #pragma unroll
        for (int k = 0; k < KE; k++) { att[k] = lg[k]/se; g_att[b*KE+k] = att[k]; }
    }
    __syncthreads();
    float bv = 0.f;
    #pragma unroll
    for (int k = 0; k < KE; k++) bv += att[k]*biases[k*FFo + t];
    g_bias[b*FFo + t] = bv;
}

// ---------------- stage 3: mix expert kernels -> per-sample W (tf32) ----------------
__global__ void mix_kernel(const float* __restrict__ kernels) {
    int r = blockIdx.x, b = blockIdx.y, f = threadIdx.x;
    const float* ab = g_att + b*KE;
    size_t off = (size_t)r*FFo + f;
    float s = ab[0]*kernels[off]
            + ab[1]*kernels[off + (size_t)K3*FFo]
            + ab[2]*kernels[off + 2*(size_t)K3*FFo]
            + ab[3]*kernels[off + 3*(size_t)K3*FFo];
    g_wmix[((size_t)b*K3 + r)*FFo + f] = __uint_as_float(f2tf32(s));
}

// ---------------- stage 4: implicit-GEMM conv, tf32 mma.sync + cp.async ----------------
__global__ __launch_bounds__(256, 2) void conv_kernel(float* __restrict__ out) {
    extern __shared__ __align__(16) float sm[];
    float* As = sm;                         // [2][TM][LDA]
    float* Bs = sm + 2*A_STAGE_F;           // [2][KC][LDB]

    const int b = blockIdx.z, mtile = blockIdx.y, ntile = blockIdx.x;
    const int tid = threadIdx.x;
    const int lane = tid & 31, wid = tid >> 5;
    const int wm = wid & 3, wn = wid >> 2;       // 4 M-warps x 2 N-warps
    const int gid = lane >> 2, tig = lane & 3;

    const float* xb = g_xr + (size_t)b*HW*CC;
    const float* Wb = g_wmix + (size_t)b*K3*FFo;

    float acc[2][8][4];
    #pragma unroll
    for (int i=0;i<2;i++)
        #pragma unroll
        for (int j=0;j<8;j++)
            #pragma unroll
            for (int q=0;q<4;q++) acc[i][j][q]=0.f;

    // A-copy coords: 1024 chunks of 16B -> 4 per thread
    int a_row[4], a_q[4], a_h[4], a_w[4];
    #pragma unroll
    for (int i=0;i<4;i++){
        int idx = i*256 + tid;
        a_row[i] = idx >> 3;
        a_q[i]   = idx & 7;
        int m = mtile*TM + a_row[i];
        a_h[i] = m >> 6;
        a_w[i] = m & 63;
    }
    // B-copy coords
    int b_row[4], b_col[4];
    #pragma unroll
    for (int i=0;i<4;i++){
        int idx = i*256 + tid;
        b_row[i] = idx >> 5;
        b_col[i] = (idx & 31) << 2;
    }

    const uint32_t As_u = s2u(As);
    const uint32_t Bs_u = s2u(Bs);

    auto issue = [&](int chunk, int buf){
        int tap = chunk >> 3;                 // 0..8 -> (kh,kw)
        int dy = tap/3 - 1, dx = tap%3 - 1;
        int c0 = (chunk & 7) << 5;            // channel base
        uint32_t Ad = As_u + (buf*A_STAGE_F)*4;
        #pragma unroll
        for (int i=0;i<4;i++){
            int h = a_h[i] + dy, w = a_w[i] + dx;
            bool ok = ((unsigned)h < HH) && ((unsigned)w < WW);
            const float* src = ok ? (xb + ((size_t)(h*WW + w))*CC + c0 + a_q[i]*4) : xb;
            cp16(Ad + (a_row[i]*LDA + a_q[i]*4)*4, src, ok ? 16u : 0u);
        }
        uint32_t Bd = Bs_u + (buf*B_STAGE_F)*4;
        const float* Wc = Wb + ((size_t)chunk*KC)*FFo + ntile*TN;
        #pragma unroll
        for (int i=0;i<4;i++)
            cp16(Bd + (b_row[i]*LDB + b_col[i])*4,
                 Wc + (size_t)b_row[i]*FFo + b_col[i], 16u);
        asm volatile("cp.async.commit_group;" ::: "memory");
    };

    auto compute = [&](int buf){
        const float* Ab = As + buf*A_STAGE_F + (wm*32)*LDA;
        const float* Bb = Bs + buf*B_STAGE_F + wn*64;
        #pragma unroll
        for (int ks=0; ks<4; ks++){
            int k0 = ks*8;
            uint32_t af[2][4];
            #pragma unroll
            for (int mi=0; mi<2; mi++){
                int r = mi*16 + gid;
                af[mi][0] = __float_as_uint(Ab[r*LDA + k0 + tig]);
                af[mi][1] = __float_as_uint(Ab[(r+8)*LDA + k0 + tig]);
                af[mi][2] = __float_as_uint(Ab[r*LDA + k0 + tig + 4]);
                af[mi][3] = __float_as_uint(Ab[(r+8)*LDA + k0 + tig + 4]);
            }
            uint32_t bf[8][2];
            #pragma unroll
            for (int nj=0; nj<8; nj++){
                int n = nj*8 + gid;
                bf[nj][0] = __float_as_uint(Bb[(k0 + tig)*LDB + n]);
                bf[nj][1] = __float_as_uint(Bb[(k0 + tig + 4)*LDB + n]);
            }
            #pragma unroll
            for (int mi=0; mi<2; mi++)
                #pragma unroll
                for (int nj=0; nj<8; nj++){
                    asm volatile(
                      "mma.sync.aligned.m16n8k8.row.col.f32.tf32.tf32.f32 "
                      "{%0,%1,%2,%3}, {%4,%5,%6,%7}, {%8,%9}, {%0,%1,%2,%3};\n"
                      : "+f"(acc[mi][nj][0]), "+f"(acc[mi][nj][1]),
                        "+f"(acc[mi][nj][2]), "+f"(acc[mi][nj][3])
                      : "r"(af[mi][0]), "r"(af[mi][1]), "r"(af[mi][2]), "r"(af[mi][3]),
                        "r"(bf[nj][0]), "r"(bf[nj][1]));
                }
        }
    };

    issue(0, 0);
    int buf = 0;
    for (int ch = 0; ch < NCHUNK; ch++){
        if (ch + 1 < NCHUNK){
            issue(ch+1, buf^1);
            asm volatile("cp.async.wait_group 1;" ::: "memory");
        } else {
            asm volatile("cp.async.wait_group 0;" ::: "memory");
        }
        __syncthreads();
        compute(buf);
        __syncthreads();
        buf ^= 1;
    }

    // epilogue: add routed bias, store fp32
    float* ob = out + ((size_t)b*HW + mtile*TM + wm*32)*FFo + ntile*TN + wn*64;
    const float* bb = g_bias + b*FFo + ntile*TN + wn*64;
    #pragma unroll
    for (int mi=0; mi<2; mi++)
        #pragma unroll
        for (int nj=0; nj<8; nj++){
            int col = nj*8 + tig*2;
            float bv0 = bb[col], bv1 = bb[col+1];
            int r0 = mi*16 + gid;
            float2 v0 = make_float2(acc[mi][nj][0]+bv0, acc[mi][nj][1]+bv1);
            float2 v1 = make_float2(acc[mi][nj][2]+bv0, acc[mi][nj][3]+bv1);
            *reinterpret_cast<float2*>(ob + (size_t)r0*FFo + col) = v0;
            *reinterpret_cast<float2*>(ob + (size_t)(r0+8)*FFo + col) = v1;
        }
}

// ---------------- launch ----------------
extern "C" void kernel_launch(void* const* d_in, const int* in_sizes, int n_in,
                              void* d_out, int out_size) {
    (void)in_sizes; (void)n_in; (void)out_size;
    const float* x       = (const float*)d_in[0];
    const float* kernels = (const float*)d_in[1];
    const float* biases  = (const float*)d_in[2];
    const float* w1      = (const float*)d_in[3];
    const float* b1      = (const float*)d_in[4];
    const float* w2      = (const float*)d_in[5];
    const float* b2      = (const float*)d_in[6];
    float* out = (float*)d_out;

    pool_partial_kernel<<<dim3(NB,32), 256>>>(x);
    routing_kernel<<<NB, 256>>>(w1, b1, w2, b2, biases);
    mix_kernel<<<dim3(K3,NB), 256>>>(kernels);

    (void)cudaFuncSetAttribute(conv_kernel, cudaFuncAttributeMaxDynamicSharedMemorySize, SMEM_BYTES);
    conv_kernel<<<dim3(2,32,NB), 256, SMEM_BYTES>>>(out);
}